// round 17
// baseline (speedup 1.0000x reference)
#include <cuda_runtime.h>
#include <math.h>

// Cross-block accumulator + arrival counter. Initially zero; the last
// finishing block resets them, so every launch (and graph replay) starts
// from the same state.
__device__ float        g_sum = 0.0f;
__device__ unsigned int g_cnt = 0u;

// One warp per patch (4 patches per 128-thread block). Lanes = columns,
// warp walks the 32 rows. Block-level reduce + single atomic per block,
// last block finalizes the output.
__global__ void __launch_bounds__(128)
patch_corr_fused_kernel(const float* __restrict__ pred,
                        const float* __restrict__ gt,
                        const int* __restrict__ x0,
                        const int* __restrict__ y0,
                        const int* __restrict__ boxp,
                        int n, int W,
                        float* __restrict__ out) {
    __shared__ float sh[4];
    int warp_in_blk = (int)(threadIdx.x >> 5);
    int warp_id = (int)(blockIdx.x * (blockDim.x >> 5)) + warp_in_blk;
    int lane = threadIdx.x & 31;

    float contrib = 0.0f;  // (1 - co) for this warp's patch, on lane 0

    if (warp_id < n) {
        int box = boxp ? __ldg(boxp) : 32;
        int x = __ldg(x0 + warp_id);
        int y = __ldg(y0 + warp_id);
        const float* pbase = pred + (size_t)x * (size_t)W + y + lane;
        const float* gbase = gt   + (size_t)x * (size_t)W + y + lane;

        float sp = 0.f, sg = 0.f, spp = 0.f, sgg = 0.f, spg = 0.f;

        if (box == 32) {
            // Fast path: one column per lane. Unroll 8 keeps ~16 LDGs in
            // flight per warp (well above the ~3 needed to cover DRAM
            // latency at this occupancy) while limiting the front-batched
            // burst that causes cross-CTA L1tex-queue spread.
            #pragma unroll 8
            for (int r = 0; r < 32; ++r) {
                float p = __ldg(pbase + (size_t)r * W);
                float g = __ldg(gbase + (size_t)r * W);
                sp += p;
                sg += g;
                spp = fmaf(p, p, spp);
                sgg = fmaf(g, g, sgg);
                spg = fmaf(p, g, spg);
            }
        } else {
            const float* pb = pbase - lane;
            const float* gb = gbase - lane;
            for (int r = 0; r < box; ++r) {
                const float* pr = pb + (size_t)r * W;
                const float* gr = gb + (size_t)r * W;
                for (int c = lane; c < box; c += 32) {
                    float p = __ldg(pr + c);
                    float g = __ldg(gr + c);
                    sp += p;
                    sg += g;
                    spp = fmaf(p, p, spp);
                    sgg = fmaf(g, g, sgg);
                    spg = fmaf(p, g, spg);
                }
            }
        }

        #pragma unroll
        for (int o = 16; o > 0; o >>= 1) {
            sp  += __shfl_xor_sync(0xffffffffu, sp,  o);
            sg  += __shfl_xor_sync(0xffffffffu, sg,  o);
            spp += __shfl_xor_sync(0xffffffffu, spp, o);
            sgg += __shfl_xor_sync(0xffffffffu, sgg, o);
            spg += __shfl_xor_sync(0xffffffffu, spg, o);
        }

        if (lane == 0) {
            float P = (float)(box * box);
            float mp = sp / P;
            float mg = sg / P;
            float varp = (spp - sp * mp) / (P - 1.0f);  // unbiased (ddof=1)
            float varg = (sgg - sg * mg) / (P - 1.0f);
            float cov  = (spg - sp * mg) / P;           // mean of centered product
            float co = cov / ((sqrtf(varp) + 1e-6f) * (sqrtf(varg) + 1e-6f));
            contrib = 1.0f - co;
        }
    }

    // Block reduce: 4 per-warp contributions -> one value.
    if (lane == 0) sh[warp_in_blk] = contrib;
    __syncthreads();

    if (threadIdx.x == 0) {
        float bsum = 0.f;
        #pragma unroll
        for (int i = 0; i < 4; ++i) bsum += sh[i];
        atomicAdd(&g_sum, bsum);
        __threadfence();
        unsigned int arrived = atomicAdd(&g_cnt, 1u);
        if (arrived == gridDim.x - 1u) {
            // Last block: all g_sum adds are visible (fence before each
            // counter increment). Read total, finalize, reset state.
            float total = atomicAdd(&g_sum, 0.0f);
            out[0] = total / (float)n;
            g_sum = 0.0f;
            g_cnt = 0u;
        }
    }
}

extern "C" void kernel_launch(void* const* d_in, const int* in_sizes, int n_in,
                              void* d_out, int out_size) {
    const float* pred = (const float*)d_in[0];
    const float* gt   = (const float*)d_in[1];
    const int*   x0   = (const int*)d_in[2];
    const int*   y0   = (const int*)d_in[3];
    const int*   boxp = (n_in >= 5) ? (const int*)d_in[4] : nullptr;

    int n = in_sizes[2];  // n_corr
    // C=1; image is square H*W = in_sizes[0]
    int W = (int)(sqrt((double)in_sizes[0]) + 0.5);

    int threads = 128;
    int warps_per_block = threads / 32;
    int blocks = (n + warps_per_block - 1) / warps_per_block;
    patch_corr_fused_kernel<<<blocks, threads>>>(pred, gt, x0, y0, boxp, n, W,
                                                 (float*)d_out);
}